// round 1
// baseline (speedup 1.0000x reference)
#include <cuda_runtime.h>
#include <math.h>

#define N_NODES  50000
#define F_IN     256
#define HEADS    3
#define OUT_C    128
#define HO       384      // HEADS*OUT_C
#define NG       64
#define NC       2
#define E_MAX    800000
#define EN_MAX   (E_MAX + N_NODES)
#define SLOPE    0.2f

// ---------------- scratch (device globals; no allocs allowed) ----------------
__device__ float g_h[N_NODES * HO];          // x @ W            (76.8 MB)
__device__ float g_out[N_NODES * HO];        // aggregated       (76.8 MB)
__device__ float g_a_src[N_NODES * HEADS];
__device__ float g_a_dst[N_NODES * HEADS];
__device__ float g_emax[N_NODES * HEADS];
__device__ float g_denom[N_NODES * HEADS];
__device__ float g_ex[EN_MAX * HEADS];       // per-edge exp     (10.2 MB)
__device__ float g_pooled[NG * HO];
__device__ float g_cnt[NG];

// ---------------- helpers ----------------
__device__ __forceinline__ void atomicMaxFloat(float* addr, float val) {
    if (val >= 0.0f)
        atomicMax((int*)addr, __float_as_int(val));
    else
        atomicMin((unsigned int*)addr, __float_as_uint(val));
}

__device__ __forceinline__ void red_add_v4(float* addr, float4 v) {
    asm volatile("red.global.add.v4.f32 [%0], {%1,%2,%3,%4};"
                 :: "l"(addr), "f"(v.x), "f"(v.y), "f"(v.z), "f"(v.w)
                 : "memory");
}

// ---------------- K0: init scratch ----------------
__global__ void k_init(int n) {
    int i = blockIdx.x * blockDim.x + threadIdx.x;
    int total = n * HO;
    int stride = gridDim.x * blockDim.x;
    for (int j = i; j < total; j += stride) g_out[j] = 0.0f;
    if (i < n * HEADS) { g_emax[i] = -INFINITY; g_denom[i] = 0.0f; }
    if (i < NG * HO) g_pooled[i] = 0.0f;
    if (i < NG) g_cnt[i] = 0.0f;
}

// ---------------- K1: GEMM  h = x @ W  (n x 256) @ (256 x 384) ---------------
// 128x64 block tile, BK=16, 256 threads, 8x4 per thread.
__global__ void __launch_bounds__(256) k_gemm(const float* __restrict__ A,
                                              const float* __restrict__ B,
                                              int n) {
    __shared__ float As[16][132];   // transposed A tile (k-major), padded
    __shared__ float Bs[16][64];

    const int row0 = blockIdx.y * 128;
    const int col0 = blockIdx.x * 64;
    const int t = threadIdx.x;
    const int tx = t & 15;          // col group
    const int ty = t >> 4;          // row group

    float acc[8][4];
#pragma unroll
    for (int i = 0; i < 8; i++)
#pragma unroll
        for (int j = 0; j < 4; j++) acc[i][j] = 0.0f;

    for (int kk = 0; kk < F_IN; kk += 16) {
        // load A tile: 128 rows x 16 cols = 512 float4s, 2 per thread
#pragma unroll
        for (int l = 0; l < 2; l++) {
            int q = t + l * 256;
            int r = q >> 2;          // 0..127
            int c4 = q & 3;          // 0..3
            int grow = row0 + r;
            float4 v = make_float4(0.f, 0.f, 0.f, 0.f);
            if (grow < n)
                v = *(const float4*)&A[grow * F_IN + kk + c4 * 4];
            As[c4 * 4 + 0][r] = v.x;
            As[c4 * 4 + 1][r] = v.y;
            As[c4 * 4 + 2][r] = v.z;
            As[c4 * 4 + 3][r] = v.w;
        }
        // load B tile: 16 rows x 64 cols = 256 float4s, 1 per thread
        {
            int r = t >> 4;          // 0..15
            int c4 = t & 15;         // 0..15
            float4 v = *(const float4*)&B[(kk + r) * HO + col0 + c4 * 4];
            *(float4*)&Bs[r][c4 * 4] = v;
        }
        __syncthreads();

#pragma unroll
        for (int k = 0; k < 16; k++) {
            float4 a0 = *(float4*)&As[k][ty * 8];
            float4 a1 = *(float4*)&As[k][ty * 8 + 4];
            float4 b  = *(float4*)&Bs[k][tx * 4];
            float av[8] = {a0.x, a0.y, a0.z, a0.w, a1.x, a1.y, a1.z, a1.w};
            float bv[4] = {b.x, b.y, b.z, b.w};
#pragma unroll
            for (int i = 0; i < 8; i++)
#pragma unroll
                for (int j = 0; j < 4; j++)
                    acc[i][j] = fmaf(av[i], bv[j], acc[i][j]);
        }
        __syncthreads();
    }

#pragma unroll
    for (int i = 0; i < 8; i++) {
        int grow = row0 + ty * 8 + i;
        if (grow < n) {
            float4 v = make_float4(acc[i][0], acc[i][1], acc[i][2], acc[i][3]);
            *(float4*)&g_h[grow * HO + col0 + tx * 4] = v;
        }
    }
}

// ---------------- K2: per-node attention logits ----------------
// one warp per (node, head)
__global__ void k_att(const float* __restrict__ att_src,
                      const float* __restrict__ att_dst, int n) {
    int w = (blockIdx.x * blockDim.x + threadIdx.x) >> 5;
    int lane = threadIdx.x & 31;
    if (w >= n * HEADS) return;
    int node = w / HEADS;
    int head = w - node * HEADS;

    float4 hv = *(const float4*)&g_h[node * HO + head * OUT_C + lane * 4];
    float4 as = *(const float4*)&att_src[head * OUT_C + lane * 4];
    float4 ad = *(const float4*)&att_dst[head * OUT_C + lane * 4];

    float s = hv.x * as.x + hv.y * as.y + hv.z * as.z + hv.w * as.w;
    float d = hv.x * ad.x + hv.y * ad.y + hv.z * ad.z + hv.w * ad.w;
#pragma unroll
    for (int o = 16; o > 0; o >>= 1) {
        s += __shfl_xor_sync(0xFFFFFFFFu, s, o);
        d += __shfl_xor_sync(0xFFFFFFFFu, d, o);
    }
    if (lane == 0) {
        g_a_src[w] = s;
        g_a_dst[w] = d;
    }
}

// ---------------- K3: segment max over edges (incl. self-loops) --------------
__global__ void k_edge_max(const int* __restrict__ ei, int E, int n) {
    int e = blockIdx.x * blockDim.x + threadIdx.x;
    int total = E + n;
    if (e >= total) return;
    int s, d;
    if (e < E) { s = ei[e]; d = ei[E + e]; }
    else       { s = d = e - E; }
#pragma unroll
    for (int h = 0; h < HEADS; h++) {
        float v = g_a_src[s * HEADS + h] + g_a_dst[d * HEADS + h];
        v = v > 0.0f ? v : SLOPE * v;
        atomicMaxFloat(&g_emax[d * HEADS + h], v);
    }
}

// ---------------- K4: exp + segment sum ----------------
__global__ void k_edge_exp(const int* __restrict__ ei, int E, int n) {
    int e = blockIdx.x * blockDim.x + threadIdx.x;
    int total = E + n;
    if (e >= total) return;
    int s, d;
    if (e < E) { s = ei[e]; d = ei[E + e]; }
    else       { s = d = e - E; }
#pragma unroll
    for (int h = 0; h < HEADS; h++) {
        float v = g_a_src[s * HEADS + h] + g_a_dst[d * HEADS + h];
        v = v > 0.0f ? v : SLOPE * v;
        float ex = expf(v - g_emax[d * HEADS + h]);
        g_ex[e * HEADS + h] = ex;
        atomicAdd(&g_denom[d * HEADS + h], ex);
    }
}

// ---------------- K5: weighted scatter-add aggregation -----------------------
// one warp per edge; 3 heads x (float4 load + red.v4)
__global__ void k_scatter(const int* __restrict__ ei, int E, int n) {
    int w = (blockIdx.x * blockDim.x + threadIdx.x) >> 5;
    int lane = threadIdx.x & 31;
    int total = E + n;
    if (w >= total) return;
    int s, d;
    if (w < E) { s = ei[w]; d = ei[E + w]; }
    else       { s = d = w - E; }
#pragma unroll
    for (int h = 0; h < HEADS; h++) {
        float alpha = g_ex[w * HEADS + h] /
                      (g_denom[d * HEADS + h] + 1e-16f);
        float4 hv = *(const float4*)&g_h[s * HO + h * OUT_C + lane * 4];
        float4 m = make_float4(hv.x * alpha, hv.y * alpha,
                               hv.z * alpha, hv.w * alpha);
        red_add_v4(&g_out[d * HO + h * OUT_C + lane * 4], m);
    }
}

// ---------------- K6: relu(+bias) and mean-pool scatter ----------------------
// one warp per node
__global__ void k_pool(const int* __restrict__ batch,
                       const float* __restrict__ bias, int n) {
    int w = (blockIdx.x * blockDim.x + threadIdx.x) >> 5;
    int lane = threadIdx.x & 31;
    if (w >= n) return;
    int g = batch[w];
#pragma unroll
    for (int j = 0; j < 3; j++) {
        int off = j * 128 + lane * 4;
        float4 v = *(const float4*)&g_out[w * HO + off];
        float4 b = *(const float4*)&bias[off];
        float4 r = make_float4(fmaxf(v.x + b.x, 0.f), fmaxf(v.y + b.y, 0.f),
                               fmaxf(v.z + b.z, 0.f), fmaxf(v.w + b.w, 0.f));
        red_add_v4(&g_pooled[g * HO + off], r);
    }
    if (lane == 0) atomicAdd(&g_cnt[g], 1.0f);
}

// ---------------- K7: mean + FC ----------------
__global__ void k_final(const float* __restrict__ fc_w,
                        const float* __restrict__ fc_b,
                        float* __restrict__ out) {
    int t = threadIdx.x;           // 128 threads: (g, c)
    if (t >= NG * NC) return;
    int g = t >> 1;
    int c = t & 1;
    float cnt = fmaxf(g_cnt[g], 1.0f);
    float s = 0.0f;
    for (int k = 0; k < HO; k++)
        s += g_pooled[g * HO + k] * fc_w[k * NC + c];
    out[t] = s / cnt + fc_b[c];
}

// ---------------- launch ----------------
extern "C" void kernel_launch(void* const* d_in, const int* in_sizes, int n_in,
                              void* d_out, int out_size) {
    const float* x        = (const float*)d_in[0];
    const int*   ei       = (const int*)  d_in[1];
    const int*   batch    = (const int*)  d_in[2];
    const float* W        = (const float*)d_in[3];
    const float* att_src  = (const float*)d_in[4];
    const float* att_dst  = (const float*)d_in[5];
    const float* bias     = (const float*)d_in[6];
    const float* fc_w     = (const float*)d_in[7];
    const float* fc_b     = (const float*)d_in[8];
    float* out = (float*)d_out;

    const int n = in_sizes[0] / F_IN;       // 50000
    const int E = in_sizes[1] / 2;          // 800000
    const int EN = E + n;

    // K0: init
    {
        int total = n * HO;
        int blocks = (total + 255) / 256;
        k_init<<<blocks, 256>>>(n);
    }
    // K1: GEMM
    {
        dim3 grid(HO / 64, (n + 127) / 128);
        k_gemm<<<grid, 256>>>(x, W, n);
    }
    // K2: attention logits
    {
        int warps = n * HEADS;
        int blocks = (warps * 32 + 255) / 256;
        k_att<<<blocks, 256>>>(att_src, att_dst, n);
    }
    // K3: segment max
    k_edge_max<<<(EN + 255) / 256, 256>>>(ei, E, n);
    // K4: exp + denom
    k_edge_exp<<<(EN + 255) / 256, 256>>>(ei, E, n);
    // K5: scatter aggregate
    {
        int blocks = (EN * 32 + 255) / 256;
        k_scatter<<<blocks, 256>>>(ei, E, n);
    }
    // K6: pool
    {
        int blocks = (n * 32 + 255) / 256;
        k_pool<<<blocks, 256>>>(batch, bias, n);
    }
    // K7: FC
    k_final<<<1, 128>>>(fc_w, fc_b, out);
}

// round 2
// speedup vs baseline: 1.8009x; 1.8009x over previous
#include <cuda_runtime.h>
#include <math.h>

#define N_NODES  50000
#define F_IN     256
#define HEADS    3
#define OUT_C    128
#define HO       384      // HEADS*OUT_C
#define NG       64
#define NC       2
#define E_MAX    800000
#define SLOPE    0.2f

// ---------------- scratch (device globals; no allocs allowed) ----------------
__device__ float g_h[N_NODES * HO];          // x @ W  (76.8 MB)
__device__ float g_a_src[N_NODES * HEADS];
__device__ float g_a_dst[N_NODES * HEADS];
__device__ int   g_deg[N_NODES];
__device__ int   g_roff[N_NODES];            // exclusive row offsets
__device__ int   g_cursor[N_NODES];
__device__ int   g_csr[E_MAX];               // src ids grouped by dst
__device__ int   g_scan_incl[N_NODES];
__device__ int   g_bsum[256];
__device__ float g_out2[NG * NC];            // per-graph FC-projected sums
__device__ float g_cnt[NG];

// ---------------- K0: init ----------------
__global__ void k_init(int n) {
    int i = blockIdx.x * blockDim.x + threadIdx.x;
    if (i < n) g_deg[i] = 0;
    if (i < NG * NC) g_out2[i] = 0.0f;
    if (i < NG) g_cnt[i] = 0.0f;
}

// ---------------- K1: GEMM  h = x @ W  (n x 256) @ (256 x 384) ---------------
// 128x128 tile, BK=8, 256 threads, 8x8 per thread (2x2 blocks of 4x4)
__global__ void __launch_bounds__(256) k_gemm(const float* __restrict__ A,
                                              const float* __restrict__ B,
                                              int n) {
    __shared__ float As[8][132];    // k-major (transposed), padded
    __shared__ float Bs[8][128];

    const int row0 = blockIdx.y * 128;
    const int col0 = blockIdx.x * 128;
    const int t  = threadIdx.x;
    const int tx = t & 15;          // 0..15 -> cols tx*4 and tx*4+64
    const int ty = t >> 4;          // 0..15 -> rows ty*4 and ty*4+64

    float acc[2][2][4][4];
#pragma unroll
    for (int a = 0; a < 2; a++)
#pragma unroll
        for (int b = 0; b < 2; b++)
#pragma unroll
            for (int i = 0; i < 4; i++)
#pragma unroll
                for (int j = 0; j < 4; j++) acc[a][b][i][j] = 0.0f;

    const int ar  = t >> 1;         // 0..127  (A load row within tile)
    const int ac4 = t & 1;          // 0..1    (A load col group of 4)
    const int br  = t >> 5;         // 0..7    (B load row)
    const int bc  = t & 31;         // 0..31   (B load col group of 4)

    for (int kk = 0; kk < F_IN; kk += 8) {
        {
            int grow = row0 + ar;
            float4 v = make_float4(0.f, 0.f, 0.f, 0.f);
            if (grow < n)
                v = *(const float4*)&A[grow * F_IN + kk + ac4 * 4];
            As[ac4 * 4 + 0][ar] = v.x;
            As[ac4 * 4 + 1][ar] = v.y;
            As[ac4 * 4 + 2][ar] = v.z;
            As[ac4 * 4 + 3][ar] = v.w;
        }
        {
            float4 v = *(const float4*)&B[(kk + br) * HO + col0 + bc * 4];
            *(float4*)&Bs[br][bc * 4] = v;
        }
        __syncthreads();

#pragma unroll
        for (int k = 0; k < 8; k++) {
            float4 a0 = *(float4*)&As[k][ty * 4];
            float4 a1 = *(float4*)&As[k][ty * 4 + 64];
            float4 b0 = *(float4*)&Bs[k][tx * 4];
            float4 b1 = *(float4*)&Bs[k][tx * 4 + 64];
            float av[2][4] = {{a0.x, a0.y, a0.z, a0.w}, {a1.x, a1.y, a1.z, a1.w}};
            float bv[2][4] = {{b0.x, b0.y, b0.z, b0.w}, {b1.x, b1.y, b1.z, b1.w}};
#pragma unroll
            for (int a = 0; a < 2; a++)
#pragma unroll
                for (int b = 0; b < 2; b++)
#pragma unroll
                    for (int i = 0; i < 4; i++)
#pragma unroll
                        for (int j = 0; j < 4; j++)
                            acc[a][b][i][j] = fmaf(av[a][i], bv[b][j], acc[a][b][i][j]);
        }
        __syncthreads();
    }

#pragma unroll
    for (int a = 0; a < 2; a++)
#pragma unroll
        for (int i = 0; i < 4; i++) {
            int grow = row0 + ty * 4 + a * 64 + i;
            if (grow < n) {
#pragma unroll
                for (int b = 0; b < 2; b++) {
                    float4 v = make_float4(acc[a][b][i][0], acc[a][b][i][1],
                                           acc[a][b][i][2], acc[a][b][i][3]);
                    *(float4*)&g_h[grow * HO + col0 + tx * 4 + b * 64] = v;
                }
            }
        }
}

// ---------------- K2: per-node attention logits ----------------
__global__ void k_att(const float* __restrict__ att_src,
                      const float* __restrict__ att_dst, int n) {
    int w = (blockIdx.x * blockDim.x + threadIdx.x) >> 5;
    int lane = threadIdx.x & 31;
    if (w >= n * HEADS) return;
    int node = w / HEADS;
    int head = w - node * HEADS;

    float4 hv = *(const float4*)&g_h[node * HO + head * OUT_C + lane * 4];
    float4 as = *(const float4*)&att_src[head * OUT_C + lane * 4];
    float4 ad = *(const float4*)&att_dst[head * OUT_C + lane * 4];

    float s = hv.x * as.x + hv.y * as.y + hv.z * as.z + hv.w * as.w;
    float d = hv.x * ad.x + hv.y * ad.y + hv.z * ad.z + hv.w * ad.w;
#pragma unroll
    for (int o = 16; o > 0; o >>= 1) {
        s += __shfl_xor_sync(0xFFFFFFFFu, s, o);
        d += __shfl_xor_sync(0xFFFFFFFFu, d, o);
    }
    if (lane == 0) {
        g_a_src[w] = s;
        g_a_dst[w] = d;
    }
}

// ---------------- K3: degree histogram ----------------
__global__ void k_hist(const int* __restrict__ ei, int E) {
    int e = blockIdx.x * blockDim.x + threadIdx.x;
    if (e >= E) return;
    atomicAdd(&g_deg[ei[E + e]], 1);
}

// ---------------- K4a/b/c: exclusive scan of degrees ----------------
__global__ void k_scan1(int n) {
    __shared__ int s[256];
    int b = blockIdx.x, t = threadIdx.x;
    int i = b * 256 + t;
    int v = (i < n) ? g_deg[i] : 0;
    s[t] = v;
    __syncthreads();
#pragma unroll
    for (int off = 1; off < 256; off <<= 1) {
        int u = (t >= off) ? s[t - off] : 0;
        __syncthreads();
        s[t] += u;
        __syncthreads();
    }
    if (i < n) g_scan_incl[i] = s[t];
    if (t == 255) g_bsum[b] = s[255];
}

__global__ void k_scan2(int nblk) {
    __shared__ int s[256];
    int t = threadIdx.x;
    int orig = (t < nblk) ? g_bsum[t] : 0;
    s[t] = orig;
    __syncthreads();
#pragma unroll
    for (int off = 1; off < 256; off <<= 1) {
        int u = (t >= off) ? s[t - off] : 0;
        __syncthreads();
        s[t] += u;
        __syncthreads();
    }
    g_bsum[t] = s[t] - orig;   // exclusive
}

__global__ void k_scan3(int n) {
    int i = blockIdx.x * blockDim.x + threadIdx.x;
    if (i >= n) return;
    int r = g_scan_incl[i] - g_deg[i] + g_bsum[i >> 8];
    g_roff[i] = r;
    g_cursor[i] = r;
}

// ---------------- K5: CSR fill ----------------
__global__ void k_fill(const int* __restrict__ ei, int E) {
    int e = blockIdx.x * blockDim.x + threadIdx.x;
    if (e >= E) return;
    int s = ei[e];
    int d = ei[E + e];
    int pos = atomicAdd(&g_cursor[d], 1);
    g_csr[pos] = s;
}

// ---------------- K6: fused softmax + aggregate + relu + FC-project ----------
// one warp per dst node
__global__ void __launch_bounds__(256) k_agg(const int* __restrict__ batch,
                                             const float* __restrict__ bias,
                                             const float* __restrict__ fc_w,
                                             int n) {
    int d = (blockIdx.x * blockDim.x + threadIdx.x) >> 5;
    int lane = threadIdx.x & 31;
    if (d >= n) return;

    // a_dst for this node (lane h<3 holds head h)
    float my_adst = (lane < 3) ? g_a_dst[d * HEADS + lane] : 0.0f;

    // self loop term
    float exl = 0.0f;
    if (lane < 3) {
        float v = g_a_src[d * HEADS + lane] + my_adst;
        v = v > 0.0f ? v : SLOPE * v;
        exl = expf(v);
    }
    float e0 = __shfl_sync(0xFFFFFFFFu, exl, 0);
    float e1 = __shfl_sync(0xFFFFFFFFu, exl, 1);
    float e2 = __shfl_sync(0xFFFFFFFFu, exl, 2);

    const float4* hp = (const float4*)&g_h[(long)d * HO];
    float4 h0 = hp[lane];
    float4 h1 = hp[lane + 32];
    float4 h2 = hp[lane + 64];
    float4 acc0 = make_float4(e0 * h0.x, e0 * h0.y, e0 * h0.z, e0 * h0.w);
    float4 acc1 = make_float4(e1 * h1.x, e1 * h1.y, e1 * h1.z, e1 * h1.w);
    float4 acc2 = make_float4(e2 * h2.x, e2 * h2.y, e2 * h2.z, e2 * h2.w);
    float den0 = e0, den1 = e1, den2 = e2;

    int start = g_roff[d];
    int cnt = g_deg[d];
    int s = (cnt > 0) ? g_csr[start] : 0;
    for (int j = 0; j < cnt; j++) {
        int s_next = (j + 1 < cnt) ? g_csr[start + j + 1] : 0;
        float exe = 0.0f;
        if (lane < 3) {
            float v = g_a_src[s * HEADS + lane] + my_adst;
            v = v > 0.0f ? v : SLOPE * v;
            exe = expf(v);
        }
        float f0 = __shfl_sync(0xFFFFFFFFu, exe, 0);
        float f1 = __shfl_sync(0xFFFFFFFFu, exe, 1);
        float f2 = __shfl_sync(0xFFFFFFFFu, exe, 2);
        const float4* sp = (const float4*)&g_h[(long)s * HO];
        float4 s0 = sp[lane];
        float4 s1 = sp[lane + 32];
        float4 s2 = sp[lane + 64];
        acc0.x = fmaf(f0, s0.x, acc0.x); acc0.y = fmaf(f0, s0.y, acc0.y);
        acc0.z = fmaf(f0, s0.z, acc0.z); acc0.w = fmaf(f0, s0.w, acc0.w);
        acc1.x = fmaf(f1, s1.x, acc1.x); acc1.y = fmaf(f1, s1.y, acc1.y);
        acc1.z = fmaf(f1, s1.z, acc1.z); acc1.w = fmaf(f1, s1.w, acc1.w);
        acc2.x = fmaf(f2, s2.x, acc2.x); acc2.y = fmaf(f2, s2.y, acc2.y);
        acc2.z = fmaf(f2, s2.z, acc2.z); acc2.w = fmaf(f2, s2.w, acc2.w);
        den0 += f0; den1 += f1; den2 += f2;
        s = s_next;
    }

    float inv0 = 1.0f / (den0 + 1e-16f);
    float inv1 = 1.0f / (den1 + 1e-16f);
    float inv2 = 1.0f / (den2 + 1e-16f);

    // bias + relu, then project through fc_w  -> 2 scalars
    float c0 = 0.0f, c1 = 0.0f;
#pragma unroll
    for (int h = 0; h < 3; h++) {
        float4 a = (h == 0) ? acc0 : (h == 1) ? acc1 : acc2;
        float inv = (h == 0) ? inv0 : (h == 1) ? inv1 : inv2;
        int base = h * OUT_C + lane * 4;
        float4 b = *(const float4*)&bias[base];
        float r[4];
        r[0] = fmaxf(a.x * inv + b.x, 0.0f);
        r[1] = fmaxf(a.y * inv + b.y, 0.0f);
        r[2] = fmaxf(a.z * inv + b.z, 0.0f);
        r[3] = fmaxf(a.w * inv + b.w, 0.0f);
#pragma unroll
        for (int k = 0; k < 4; k++) {
            float2 w = *(const float2*)&fc_w[(base + k) * NC];
            c0 = fmaf(r[k], w.x, c0);
            c1 = fmaf(r[k], w.y, c1);
        }
    }
#pragma unroll
    for (int o = 16; o > 0; o >>= 1) {
        c0 += __shfl_xor_sync(0xFFFFFFFFu, c0, o);
        c1 += __shfl_xor_sync(0xFFFFFFFFu, c1, o);
    }
    if (lane == 0) {
        int g = batch[d];
        atomicAdd(&g_out2[g * NC + 0], c0);
        atomicAdd(&g_out2[g * NC + 1], c1);
        atomicAdd(&g_cnt[g], 1.0f);
    }
}

// ---------------- K7: final mean + bias ----------------
__global__ void k_final(const float* __restrict__ fc_b,
                        float* __restrict__ out) {
    int t = threadIdx.x;
    if (t >= NG * NC) return;
    int g = t >> 1;
    int c = t & 1;
    float cnt = fmaxf(g_cnt[g], 1.0f);
    out[t] = g_out2[t] / cnt + fc_b[c];
}

// ---------------- launch ----------------
extern "C" void kernel_launch(void* const* d_in, const int* in_sizes, int n_in,
                              void* d_out, int out_size) {
    const float* x       = (const float*)d_in[0];
    const int*   ei      = (const int*)  d_in[1];
    const int*   batch   = (const int*)  d_in[2];
    const float* W       = (const float*)d_in[3];
    const float* att_src = (const float*)d_in[4];
    const float* att_dst = (const float*)d_in[5];
    const float* bias    = (const float*)d_in[6];
    const float* fc_w    = (const float*)d_in[7];
    const float* fc_b    = (const float*)d_in[8];
    float* out = (float*)d_out;

    const int n = in_sizes[0] / F_IN;       // 50000
    const int E = in_sizes[1] / 2;          // 800000
    const int nblk = (n + 255) / 256;

    k_init<<<(n + 255) / 256, 256>>>(n);
    {
        dim3 grid(HO / 128, (n + 127) / 128);
        k_gemm<<<grid, 256>>>(x, W, n);
    }
    {
        int warps = n * HEADS;
        k_att<<<(warps * 32 + 255) / 256, 256>>>(att_src, att_dst, n);
    }
    k_hist<<<(E + 255) / 256, 256>>>(ei, E);
    k_scan1<<<nblk, 256>>>(n);
    k_scan2<<<1, 256>>>(nblk);
    k_scan3<<<(n + 255) / 256, 256>>>(n);
    k_fill<<<(E + 255) / 256, 256>>>(ei, E);
    k_agg<<<(n * 32 + 255) / 256, 256>>>(batch, bias, fc_w, n);
    k_final<<<1, 128>>>(fc_b, out);
}

// round 3
// speedup vs baseline: 2.0336x; 1.1292x over previous
#include <cuda_runtime.h>
#include <cuda_fp16.h>
#include <math.h>

#define N_NODES  50000
#define F_IN     256
#define HEADS    3
#define OUT_C    128
#define HO       384      // HEADS*OUT_C
#define NG       64
#define NC       2
#define E_MAX    800000
#define SLOPE    0.2f

// ---------------- scratch (device globals; no allocs allowed) ----------------
__device__ __half g_h16[N_NODES * HO];       // fp16 copy of x@W (38.4 MB)
__device__ float g_a_src[N_NODES * HEADS];
__device__ float g_a_dst[N_NODES * HEADS];
__device__ int   g_deg[N_NODES];
__device__ int   g_roff[N_NODES];
__device__ int   g_cursor[N_NODES];
__device__ int   g_csr[E_MAX];
__device__ int   g_scan_incl[N_NODES];
__device__ int   g_bsum[256];
__device__ float g_out2[NG * NC];
__device__ float g_cnt[NG];

// ---------------- f32x2 packed math ----------------
#define PACK2(out, lo, hi) \
    asm("mov.b64 %0, {%1, %2};" : "=l"(out) : "f"(lo), "f"(hi))
#define UNPACK2(lo, hi, in) \
    asm("mov.b64 {%0, %1}, %2;" : "=f"(lo), "=f"(hi) : "l"(in))
#define FMA2(d, a, b, c) \
    asm("fma.rn.f32x2 %0, %1, %2, %3;" : "=l"(d) : "l"(a), "l"(b), "l"(c))

// ---------------- K0: init ----------------
__global__ void k_init(int n) {
    int i = blockIdx.x * blockDim.x + threadIdx.x;
    if (i < n) g_deg[i] = 0;
    if (i < NG * NC) g_out2[i] = 0.0f;
    if (i < NG) g_cnt[i] = 0.0f;
}

// ---------------- K1: GEMM h = x @ W, fused epilogue -------------------------
// 128x128 tile (one head per col-tile), BK=8, 256 threads, 8x8/thread.
// Packed f32x2 accumulators. Epilogue: fp16 store + attention logit reduction.
__global__ void __launch_bounds__(256) k_gemm(const float* __restrict__ A,
                                              const float* __restrict__ B,
                                              const float* __restrict__ att_src,
                                              const float* __restrict__ att_dst,
                                              int n) {
    __shared__ float As[8][132];     // k-major (transposed), padded
    __shared__ float Bs[8][128];
    __shared__ float Ps[128][17];    // per-row partial src-logit (by tx)
    __shared__ float Pd[128][17];

    const int head = blockIdx.x;
    const int row0 = blockIdx.y * 128;
    const int col0 = head * 128;
    const int t  = threadIdx.x;
    const int tx = t & 15;           // cols tx*4 + b*64
    const int ty = t >> 4;           // rows ty*4 + a*64

    unsigned long long accp[2][2][4][2];
#pragma unroll
    for (int a = 0; a < 2; a++)
#pragma unroll
        for (int b = 0; b < 2; b++)
#pragma unroll
            for (int i = 0; i < 4; i++)
#pragma unroll
                for (int j = 0; j < 2; j++) accp[a][b][i][j] = 0ULL;

    const int ar  = t >> 1;          // 0..127
    const int ac4 = t & 1;           // 0..1
    const int br  = t >> 5;          // 0..7
    const int bc  = t & 31;          // 0..31

    for (int kk = 0; kk < F_IN; kk += 8) {
        {
            int grow = row0 + ar;
            float4 v = make_float4(0.f, 0.f, 0.f, 0.f);
            if (grow < n)
                v = *(const float4*)&A[grow * F_IN + kk + ac4 * 4];
            As[ac4 * 4 + 0][ar] = v.x;
            As[ac4 * 4 + 1][ar] = v.y;
            As[ac4 * 4 + 2][ar] = v.z;
            As[ac4 * 4 + 3][ar] = v.w;
        }
        {
            float4 v = *(const float4*)&B[(kk + br) * HO + col0 + bc * 4];
            *(float4*)&Bs[br][bc * 4] = v;
        }
        __syncthreads();

#pragma unroll
        for (int k = 0; k < 8; k++) {
            float4 a0 = *(float4*)&As[k][ty * 4];
            float4 a1 = *(float4*)&As[k][ty * 4 + 64];
            float4 b0 = *(float4*)&Bs[k][tx * 4];
            float4 b1 = *(float4*)&Bs[k][tx * 4 + 64];
            unsigned long long bp[2][2];
            PACK2(bp[0][0], b0.x, b0.y);
            PACK2(bp[0][1], b0.z, b0.w);
            PACK2(bp[1][0], b1.x, b1.y);
            PACK2(bp[1][1], b1.z, b1.w);
            float av[2][4] = {{a0.x, a0.y, a0.z, a0.w},
                              {a1.x, a1.y, a1.z, a1.w}};
#pragma unroll
            for (int a = 0; a < 2; a++)
#pragma unroll
                for (int i = 0; i < 4; i++) {
                    unsigned long long ap;
                    PACK2(ap, av[a][i], av[a][i]);
#pragma unroll
                    for (int b = 0; b < 2; b++) {
                        FMA2(accp[a][b][i][0], ap, bp[b][0], accp[a][b][i][0]);
                        FMA2(accp[a][b][i][1], ap, bp[b][1], accp[a][b][i][1]);
                    }
                }
        }
        __syncthreads();
    }

    // att vectors for this thread's 8 columns
    float avs[2][4], avd[2][4];
#pragma unroll
    for (int b = 0; b < 2; b++)
#pragma unroll
        for (int j = 0; j < 4; j++) {
            int c = col0 + tx * 4 + b * 64 + j;
            avs[b][j] = att_src[c];
            avd[b][j] = att_dst[c];
        }

    // unpack, store fp16, accumulate per-row logit partials
#pragma unroll
    for (int a = 0; a < 2; a++)
#pragma unroll
        for (int i = 0; i < 4; i++) {
            int rloc = ty * 4 + a * 64 + i;
            int grow = row0 + rloc;
            float ps = 0.0f, pd = 0.0f;
            float c[2][4];
#pragma unroll
            for (int b = 0; b < 2; b++) {
                UNPACK2(c[b][0], c[b][1], accp[a][b][i][0]);
                UNPACK2(c[b][2], c[b][3], accp[a][b][i][1]);
#pragma unroll
                for (int j = 0; j < 4; j++) {
                    ps = fmaf(c[b][j], avs[b][j], ps);
                    pd = fmaf(c[b][j], avd[b][j], pd);
                }
            }
            Ps[rloc][tx] = ps;
            Pd[rloc][tx] = pd;
            if (grow < n) {
#pragma unroll
                for (int b = 0; b < 2; b++) {
                    __half2 h01 = __float22half2_rn(make_float2(c[b][0], c[b][1]));
                    __half2 h23 = __float22half2_rn(make_float2(c[b][2], c[b][3]));
                    uint2 u;
                    u.x = *(unsigned int*)&h01;
                    u.y = *(unsigned int*)&h23;
                    *(uint2*)&g_h16[(long)grow * HO + col0 + tx * 4 + b * 64] = u;
                }
            }
        }
    __syncthreads();

    // reduce 16 partials per row; threads 0-127 -> src, 128-255 -> dst
    int r = t & 127;
    int grow = row0 + r;
    if (grow < n) {
        float s = 0.0f;
        if (t < 128) {
#pragma unroll
            for (int q = 0; q < 16; q++) s += Ps[r][q];
            g_a_src[grow * HEADS + head] = s;
        } else {
#pragma unroll
            for (int q = 0; q < 16; q++) s += Pd[r][q];
            g_a_dst[grow * HEADS + head] = s;
        }
    }
}

// ---------------- K3: degree histogram ----------------
__global__ void k_hist(const int* __restrict__ ei, int E) {
    int e = blockIdx.x * blockDim.x + threadIdx.x;
    if (e >= E) return;
    atomicAdd(&g_deg[ei[E + e]], 1);
}

// ---------------- K4a/b/c: exclusive scan of degrees ----------------
__global__ void k_scan1(int n) {
    __shared__ int s[256];
    int b = blockIdx.x, t = threadIdx.x;
    int i = b * 256 + t;
    int v = (i < n) ? g_deg[i] : 0;
    s[t] = v;
    __syncthreads();
#pragma unroll
    for (int off = 1; off < 256; off <<= 1) {
        int u = (t >= off) ? s[t - off] : 0;
        __syncthreads();
        s[t] += u;
        __syncthreads();
    }
    if (i < n) g_scan_incl[i] = s[t];
    if (t == 255) g_bsum[b] = s[255];
}

__global__ void k_scan2(int nblk) {
    __shared__ int s[256];
    int t = threadIdx.x;
    int orig = (t < nblk) ? g_bsum[t] : 0;
    s[t] = orig;
    __syncthreads();
#pragma unroll
    for (int off = 1; off < 256; off <<= 1) {
        int u = (t >= off) ? s[t - off] : 0;
        __syncthreads();
        s[t] += u;
        __syncthreads();
    }
    g_bsum[t] = s[t] - orig;   // exclusive
}

__global__ void k_scan3(int n) {
    int i = blockIdx.x * blockDim.x + threadIdx.x;
    if (i >= n) return;
    int r = g_scan_incl[i] - g_deg[i] + g_bsum[i >> 8];
    g_roff[i] = r;
    g_cursor[i] = r;
}

// ---------------- K5: CSR fill ----------------
__global__ void k_fill(const int* __restrict__ ei, int E) {
    int e = blockIdx.x * blockDim.x + threadIdx.x;
    if (e >= E) return;
    int s = ei[e];
    int d = ei[E + e];
    int pos = atomicAdd(&g_cursor[d], 1);
    g_csr[pos] = s;
}

// ---------------- K6: fused softmax + aggregate + relu + FC-project ----------
// one warp per dst node; gathers fp16 h
__global__ void __launch_bounds__(256) k_agg(const int* __restrict__ batch,
                                             const float* __restrict__ bias,
                                             const float* __restrict__ fc_w,
                                             int n) {
    int d = (blockIdx.x * blockDim.x + threadIdx.x) >> 5;
    int lane = threadIdx.x & 31;
    if (d >= n) return;

    float my_adst = (lane < 3) ? g_a_dst[d * HEADS + lane] : 0.0f;

    // self-loop
    float exl = 0.0f;
    if (lane < 3) {
        float v = g_a_src[d * HEADS + lane] + my_adst;
        v = v > 0.0f ? v : SLOPE * v;
        exl = expf(v);
    }
    float e0 = __shfl_sync(0xFFFFFFFFu, exl, 0);
    float e1 = __shfl_sync(0xFFFFFFFFu, exl, 1);
    float e2 = __shfl_sync(0xFFFFFFFFu, exl, 2);

    float acc[3][4];
    float den[3] = {e0, e1, e2};
    {
        const __half* hp = &g_h16[(long)d * HO + lane * 4];
        float ee[3] = {e0, e1, e2};
#pragma unroll
        for (int h = 0; h < 3; h++) {
            uint2 u = *(const uint2*)&hp[h * OUT_C];
            float2 f01 = __half22float2(*(__half2*)&u.x);
            float2 f23 = __half22float2(*(__half2*)&u.y);
            acc[h][0] = ee[h] * f01.x;
            acc[h][1] = ee[h] * f01.y;
            acc[h][2] = ee[h] * f23.x;
            acc[h][3] = ee[h] * f23.y;
        }
    }

    int start = g_roff[d];
    int cnt = g_deg[d];
    int s = (cnt > 0) ? g_csr[start] : 0;
    for (int j = 0; j < cnt; j++) {
        int s_next = (j + 1 < cnt) ? g_csr[start + j + 1] : 0;
        float exe = 0.0f;
        if (lane < 3) {
            float v = g_a_src[s * HEADS + lane] + my_adst;
            v = v > 0.0f ? v : SLOPE * v;
            exe = expf(v);
        }
        float f0 = __shfl_sync(0xFFFFFFFFu, exe, 0);
        float f1 = __shfl_sync(0xFFFFFFFFu, exe, 1);
        float f2 = __shfl_sync(0xFFFFFFFFu, exe, 2);
        float ff[3] = {f0, f1, f2};
        const __half* sp = &g_h16[(long)s * HO + lane * 4];
#pragma unroll
        for (int h = 0; h < 3; h++) {
            uint2 u = *(const uint2*)&sp[h * OUT_C];
            float2 f01 = __half22float2(*(__half2*)&u.x);
            float2 f23 = __half22float2(*(__half2*)&u.y);
            acc[h][0] = fmaf(ff[h], f01.x, acc[h][0]);
            acc[h][1] = fmaf(ff[h], f01.y, acc[h][1]);
            acc[h][2] = fmaf(ff[h], f23.x, acc[h][2]);
            acc[h][3] = fmaf(ff[h], f23.y, acc[h][3]);
            den[h] += ff[h];
        }
        s = s_next;
    }
    // den accumulated once per lane; fix: den was incremented identically on
    // all lanes (ff same across warp) — correct as-is.

    float c0 = 0.0f, c1 = 0.0f;
#pragma unroll
    for (int h = 0; h < 3; h++) {
        float inv = 1.0f / (den[h] + 1e-16f);
        int base = h * OUT_C + lane * 4;
        float4 b = *(const float4*)&bias[base];
        float r[4];
        r[0] = fmaxf(acc[h][0] * inv + b.x, 0.0f);
        r[1] = fmaxf(acc[h][1] * inv + b.y, 0.0f);
        r[2] = fmaxf(acc[h][2] * inv + b.z, 0.0f);
        r[3] = fmaxf(acc[h][3] * inv + b.w, 0.0f);
#pragma unroll
        for (int k = 0; k < 4; k++) {
            float2 w = *(const float2*)&fc_w[(base + k) * NC];
            c0 = fmaf(r[k], w.x, c0);
            c1 = fmaf(r[k], w.y, c1);
        }
    }
#pragma unroll
    for (int o = 16; o > 0; o >>= 1) {
        c0 += __shfl_xor_sync(0xFFFFFFFFu, c0, o);
        c1 += __shfl_xor_sync(0xFFFFFFFFu, c1, o);
    }
    if (lane == 0) {
        int g = batch[d];
        atomicAdd(&g_out2[g * NC + 0], c0);
        atomicAdd(&g_out2[g * NC + 1], c1);
        atomicAdd(&g_cnt[g], 1.0f);
    }
}

// ---------------- K7: final mean + bias ----------------
__global__ void k_final(const float* __restrict__ fc_b,
                        float* __restrict__ out) {
    int t = threadIdx.x;
    if (t >= NG * NC) return;
    int g = t >> 1;
    int c = t & 1;
    float cnt = fmaxf(g_cnt[g], 1.0f);
    out[t] = g_out2[t] / cnt + fc_b[c];
}

// ---------------- launch ----------------
extern "C" void kernel_launch(void* const* d_in, const int* in_sizes, int n_in,
                              void* d_out, int out_size) {
    const float* x       = (const float*)d_in[0];
    const int*   ei      = (const int*)  d_in[1];
    const int*   batch   = (const int*)  d_in[2];
    const float* W       = (const float*)d_in[3];
    const float* att_src = (const float*)d_in[4];
    const float* att_dst = (const float*)d_in[5];
    const float* bias    = (const float*)d_in[6];
    const float* fc_w    = (const float*)d_in[7];
    const float* fc_b    = (const float*)d_in[8];
    float* out = (float*)d_out;

    const int n = in_sizes[0] / F_IN;       // 50000
    const int E = in_sizes[1] / 2;          // 800000
    const int nblk = (n + 255) / 256;

    k_init<<<(n + 255) / 256, 256>>>(n);
    {
        dim3 grid(HEADS, (n + 127) / 128);
        k_gemm<<<grid, 256>>>(x, W, att_src, att_dst, n);
    }
    k_hist<<<(E + 255) / 256, 256>>>(ei, E);
    k_scan1<<<nblk, 256>>>(n);
    k_scan2<<<1, 256>>>(nblk);
    k_scan3<<<(n + 255) / 256, 256>>>(n);
    k_fill<<<(E + 255) / 256, 256>>>(ei, E);
    k_agg<<<(n * 32 + 255) / 256, 256>>>(batch, bias, fc_w, n);
    k_final<<<1, 128>>>(fc_b, out);
}

// round 4
// speedup vs baseline: 3.1973x; 1.5722x over previous
#include <cuda_runtime.h>
#include <cuda_fp16.h>
#include <math.h>

#define N_NODES  50000
#define F_IN     256
#define HEADS    3
#define OUT_C    128
#define HO       384      // HEADS*OUT_C
#define NG       64
#define NC       2
#define E_MAX    800000
#define SLOPE    0.2f

// ---------------- scratch (device globals; no allocs allowed) ----------------
__device__ __half g_h16[N_NODES * HO];       // fp16 x@W (38.4 MB)
__device__ float g_a4_src[N_NODES * 4];      // padded [node][4] logits
__device__ float g_a4_dst[N_NODES * 4];
__device__ int   g_deg[N_NODES];
__device__ int   g_roff[N_NODES];
__device__ int   g_cursor[N_NODES];
__device__ int   g_csr[E_MAX];
__device__ int   g_scan_incl[N_NODES];
__device__ int   g_bsum[256];
__device__ float g_out2[NG * NC];
__device__ float g_cnt[NG];

// ---------------- mma / ldmatrix helpers ----------------
__device__ __forceinline__ unsigned sptr(const void* p) {
    return (unsigned)__cvta_generic_to_shared(p);
}

#define LDSM4(r0, r1, r2, r3, addr) \
    asm volatile("ldmatrix.sync.aligned.m8n8.x4.shared.b16 {%0,%1,%2,%3},[%4];" \
                 : "=r"(r0), "=r"(r1), "=r"(r2), "=r"(r3) : "r"(addr))

#define LDSM4T(r0, r1, r2, r3, addr) \
    asm volatile("ldmatrix.sync.aligned.m8n8.x4.trans.shared.b16 {%0,%1,%2,%3},[%4];" \
                 : "=r"(r0), "=r"(r1), "=r"(r2), "=r"(r3) : "r"(addr))

#define MMA16816(c, a0, a1, a2, a3, b0, b1) \
    asm volatile("mma.sync.aligned.m16n8k16.row.col.f32.f16.f16.f32 " \
                 "{%0,%1,%2,%3},{%4,%5,%6,%7},{%8,%9},{%0,%1,%2,%3};" \
                 : "+f"((c)[0]), "+f"((c)[1]), "+f"((c)[2]), "+f"((c)[3]) \
                 : "r"(a0), "r"(a1), "r"(a2), "r"(a3), "r"(b0), "r"(b1))

// ---------------- K0: init ----------------
__global__ void k_init(int n) {
    int i = blockIdx.x * blockDim.x + threadIdx.x;
    if (i < n) g_deg[i] = 0;
    if (i < NG * NC) g_out2[i] = 0.0f;
    if (i < NG) g_cnt[i] = 0.0f;
}

// ---------------- K1: tensor-core GEMM h = x @ W, fused epilogue -------------
// grid (HEADS, ceil(n/128)); block 256 = 8 warps; tile 128x128, BK=32.
// warp_m = wid&1 (64 rows), warp_n = wid>>1 (32 cols).
__global__ void __launch_bounds__(256) k_gemm(const float* __restrict__ A,
                                              const float* __restrict__ B,
                                              const float* __restrict__ att_src,
                                              const float* __restrict__ att_dst,
                                              int n) {
    __shared__ __half Ah[128 * 40];   // stride 40 halves (80 B) -> bank-rotating
    __shared__ __half Bh[32 * 136];   // stride 136 halves (272 B)
    __shared__ float Ps[128][4];
    __shared__ float Pd[128][4];

    const int head = blockIdx.x;
    const int row0 = blockIdx.y * 128;
    const int t = threadIdx.x;
    const int lane = t & 31;
    const int wid = t >> 5;
    const int warp_m = wid & 1;
    const int warp_n = wid >> 1;

    float acc[4][4][4];
#pragma unroll
    for (int mf = 0; mf < 4; mf++)
#pragma unroll
        for (int nf = 0; nf < 4; nf++)
#pragma unroll
            for (int r = 0; r < 4; r++) acc[mf][nf][r] = 0.0f;

    const int a_row = t >> 1;            // 0..127
    const int a_cb  = (t & 1) * 16;
    const int b_kr  = t >> 3;            // 0..31
    const int b_cb  = (t & 7) * 16;

    for (int kk = 0; kk < F_IN; kk += 32) {
        // ---- load A tile (fp32 -> fp16) ----
        {
            int grow = row0 + a_row;
            float4 v0 = make_float4(0.f,0.f,0.f,0.f), v1 = v0, v2 = v0, v3 = v0;
            if (grow < n) {
                const float4* ap = (const float4*)&A[(long)grow * F_IN + kk + a_cb];
                v0 = ap[0]; v1 = ap[1]; v2 = ap[2]; v3 = ap[3];
            }
            __half2 h0 = __floats2half2_rn(v0.x, v0.y);
            __half2 h1 = __floats2half2_rn(v0.z, v0.w);
            __half2 h2 = __floats2half2_rn(v1.x, v1.y);
            __half2 h3 = __floats2half2_rn(v1.z, v1.w);
            __half2 h4 = __floats2half2_rn(v2.x, v2.y);
            __half2 h5 = __floats2half2_rn(v2.z, v2.w);
            __half2 h6 = __floats2half2_rn(v3.x, v3.y);
            __half2 h7 = __floats2half2_rn(v3.z, v3.w);
            uint4 u0, u1;
            u0.x = *(unsigned*)&h0; u0.y = *(unsigned*)&h1;
            u0.z = *(unsigned*)&h2; u0.w = *(unsigned*)&h3;
            u1.x = *(unsigned*)&h4; u1.y = *(unsigned*)&h5;
            u1.z = *(unsigned*)&h6; u1.w = *(unsigned*)&h7;
            *(uint4*)&Ah[a_row * 40 + a_cb]     = u0;
            *(uint4*)&Ah[a_row * 40 + a_cb + 8] = u1;
        }
        // ---- load B tile ----
        {
            const float4* bp = (const float4*)&B[(long)(kk + b_kr) * HO + head * 128 + b_cb];
            float4 v0 = bp[0], v1 = bp[1], v2 = bp[2], v3 = bp[3];
            __half2 h0 = __floats2half2_rn(v0.x, v0.y);
            __half2 h1 = __floats2half2_rn(v0.z, v0.w);
            __half2 h2 = __floats2half2_rn(v1.x, v1.y);
            __half2 h3 = __floats2half2_rn(v1.z, v1.w);
            __half2 h4 = __floats2half2_rn(v2.x, v2.y);
            __half2 h5 = __floats2half2_rn(v2.z, v2.w);
            __half2 h6 = __floats2half2_rn(v3.x, v3.y);
            __half2 h7 = __floats2half2_rn(v3.z, v3.w);
            uint4 u0, u1;
            u0.x = *(unsigned*)&h0; u0.y = *(unsigned*)&h1;
            u0.z = *(unsigned*)&h2; u0.w = *(unsigned*)&h3;
            u1.x = *(unsigned*)&h4; u1.y = *(unsigned*)&h5;
            u1.z = *(unsigned*)&h6; u1.w = *(unsigned*)&h7;
            *(uint4*)&Bh[b_kr * 136 + b_cb]     = u0;
            *(uint4*)&Bh[b_kr * 136 + b_cb + 8] = u1;
        }
        __syncthreads();

#pragma unroll
        for (int s = 0; s < 2; s++) {
            unsigned a[4][4];
#pragma unroll
            for (int mf = 0; mf < 4; mf++) {
                unsigned addr = sptr(&Ah[(warp_m * 64 + mf * 16 + (lane & 15)) * 40 +
                                         s * 16 + (lane >> 4) * 8]);
                LDSM4(a[mf][0], a[mf][1], a[mf][2], a[mf][3], addr);
            }
            unsigned b[2][4];
#pragma unroll
            for (int nf2 = 0; nf2 < 2; nf2++) {
                unsigned addr = sptr(&Bh[(s * 16 + (lane & 15)) * 136 +
                                         warp_n * 32 + nf2 * 16 + ((lane & 16) ? 8 : 0)]);
                LDSM4T(b[nf2][0], b[nf2][1], b[nf2][2], b[nf2][3], addr);
            }
#pragma unroll
            for (int mf = 0; mf < 4; mf++)
#pragma unroll
                for (int nf = 0; nf < 4; nf++) {
                    int nf2 = nf >> 1;
                    int bo = (nf & 1) * 2;
                    MMA16816(acc[mf][nf], a[mf][0], a[mf][1], a[mf][2], a[mf][3],
                             b[nf2][bo], b[nf2][bo + 1]);
                }
        }
        __syncthreads();
    }

    // ---- epilogue: att vectors for this thread's 8 cols ----
    float avs[4][2], avd[4][2];
#pragma unroll
    for (int nf = 0; nf < 4; nf++)
#pragma unroll
        for (int j = 0; j < 2; j++) {
            int c = head * 128 + warp_n * 32 + nf * 8 + (lane & 3) * 2 + j;
            avs[nf][j] = att_src[c];
            avd[nf][j] = att_dst[c];
        }

#pragma unroll
    for (int mf = 0; mf < 4; mf++)
#pragma unroll
        for (int rh = 0; rh < 2; rh++) {
            float ps = 0.0f, pd = 0.0f;
#pragma unroll
            for (int nf = 0; nf < 4; nf++)
#pragma unroll
                for (int j = 0; j < 2; j++) {
                    float v = acc[mf][nf][rh * 2 + j];
                    ps = fmaf(v, avs[nf][j], ps);
                    pd = fmaf(v, avd[nf][j], pd);
                }
            ps += __shfl_xor_sync(0xFFFFFFFFu, ps, 1);
            ps += __shfl_xor_sync(0xFFFFFFFFu, ps, 2);
            pd += __shfl_xor_sync(0xFFFFFFFFu, pd, 1);
            pd += __shfl_xor_sync(0xFFFFFFFFu, pd, 2);
            int rloc = warp_m * 64 + mf * 16 + (lane >> 2) + rh * 8;
            if ((lane & 3) == 0) { Ps[rloc][warp_n] = ps; Pd[rloc][warp_n] = pd; }
            int grow = row0 + rloc;
            if (grow < n) {
#pragma unroll
                for (int nf = 0; nf < 4; nf++) {
                    __half2 hh = __floats2half2_rn(acc[mf][nf][rh * 2],
                                                   acc[mf][nf][rh * 2 + 1]);
                    *(__half2*)&g_h16[(long)grow * HO + head * 128 + warp_n * 32 +
                                      nf * 8 + (lane & 3) * 2] = hh;
                }
            }
        }
    __syncthreads();

    int r = t & 127;
    int grow = row0 + r;
    if (grow < n) {
        if (t < 128) {
            float s = Ps[r][0] + Ps[r][1] + Ps[r][2] + Ps[r][3];
            g_a4_src[grow * 4 + head] = s;
        } else {
            float s = Pd[r][0] + Pd[r][1] + Pd[r][2] + Pd[r][3];
            g_a4_dst[grow * 4 + head] = s;
        }
    }
}

// ---------------- K3: degree histogram ----------------
__global__ void k_hist(const int* __restrict__ ei, int E) {
    int e = blockIdx.x * blockDim.x + threadIdx.x;
    if (e >= E) return;
    atomicAdd(&g_deg[ei[E + e]], 1);
}

// ---------------- K4: scans ----------------
__global__ void k_scan1(int n) {
    __shared__ int s[256];
    int b = blockIdx.x, t = threadIdx.x;
    int i = b * 256 + t;
    int v = (i < n) ? g_deg[i] : 0;
    s[t] = v;
    __syncthreads();
#pragma unroll
    for (int off = 1; off < 256; off <<= 1) {
        int u = (t >= off) ? s[t - off] : 0;
        __syncthreads();
        s[t] += u;
        __syncthreads();
    }
    if (i < n) g_scan_incl[i] = s[t];
    if (t == 255) g_bsum[b] = s[255];
}

__global__ void k_scan2(int nblk) {
    __shared__ int s[256];
    int t = threadIdx.x;
    int orig = (t < nblk) ? g_bsum[t] : 0;
    s[t] = orig;
    __syncthreads();
#pragma unroll
    for (int off = 1; off < 256; off <<= 1) {
        int u = (t >= off) ? s[t - off] : 0;
        __syncthreads();
        s[t] += u;
        __syncthreads();
    }
    g_bsum[t] = s[t] - orig;
}

__global__ void k_scan3(int n) {
    int i = blockIdx.x * blockDim.x + threadIdx.x;
    if (i >= n) return;
    int r = g_scan_incl[i] - g_deg[i] + g_bsum[i >> 8];
    g_roff[i] = r;
    g_cursor[i] = r;
}

// ---------------- K5: CSR fill ----------------
__global__ void k_fill(const int* __restrict__ ei, int E) {
    int e = blockIdx.x * blockDim.x + threadIdx.x;
    if (e >= E) return;
    int s = ei[e];
    int d = ei[E + e];
    int pos = atomicAdd(&g_cursor[d], 1);
    g_csr[pos] = s;
}

// ---------------- K6: fused softmax + aggregate + relu + FC-project ----------
// one warp per dst node; two-phase chunked: exps staged in smem, then gather.
__global__ void __launch_bounds__(256) k_agg(const int* __restrict__ batch,
                                             const float* __restrict__ bias,
                                             const float* __restrict__ fc_w,
                                             int n) {
    __shared__ float4 buf[8][32];

    int d = (blockIdx.x * blockDim.x + threadIdx.x) >> 5;
    int lane = threadIdx.x & 31;
    int wid = (threadIdx.x >> 5);
    if (d >= n) return;

    // a_dst broadcast
    float ad = (lane < 3) ? g_a4_dst[d * 4 + lane] : 0.0f;
    float adst0 = __shfl_sync(0xFFFFFFFFu, ad, 0);
    float adst1 = __shfl_sync(0xFFFFFFFFu, ad, 1);
    float adst2 = __shfl_sync(0xFFFFFFFFu, ad, 2);

    // self-loop exp
    float exl = 0.0f;
    if (lane < 3) {
        float v = g_a4_src[d * 4 + lane] + ad;
        v = v > 0.0f ? v : SLOPE * v;
        exl = expf(v);
    }
    float e0 = __shfl_sync(0xFFFFFFFFu, exl, 0);
    float e1 = __shfl_sync(0xFFFFFFFFu, exl, 1);
    float e2 = __shfl_sync(0xFFFFFFFFu, exl, 2);

    float acc[3][4];
    {
        const __half* hp = &g_h16[(long)d * HO + lane * 4];
        float ee[3] = {e0, e1, e2};
#pragma unroll
        for (int h = 0; h < 3; h++) {
            uint2 u = *(const uint2*)&hp[h * OUT_C];
            float2 f01 = __half22float2(*(__half2*)&u.x);
            float2 f23 = __half22float2(*(__half2*)&u.y);
            acc[h][0] = ee[h] * f01.x;
            acc[h][1] = ee[h] * f01.y;
            acc[h][2] = ee[h] * f23.x;
            acc[h][3] = ee[h] * f23.y;
        }
    }

    int start = g_roff[d];
    int cnt = g_deg[d];
    float dl0 = 0.0f, dl1 = 0.0f, dl2 = 0.0f;   // per-lane denom partials

    for (int c0 = 0; c0 < cnt; c0 += 32) {
        int m = min(32, cnt - c0);
        // phase 1: one edge per lane
        int s = 0;
        float p0 = 0.0f, p1 = 0.0f, p2 = 0.0f;
        if (lane < m) {
            s = g_csr[start + c0 + lane];
            float4 a4 = *(const float4*)&g_a4_src[s * 4];
            float v0 = a4.x + adst0; v0 = v0 > 0.0f ? v0 : SLOPE * v0;
            float v1 = a4.y + adst1; v1 = v1 > 0.0f ? v1 : SLOPE * v1;
            float v2 = a4.z + adst2; v2 = v2 > 0.0f ? v2 : SLOPE * v2;
            p0 = expf(v0); p1 = expf(v1); p2 = expf(v2);
            dl0 += p0; dl1 += p1; dl2 += p2;
        }
        buf[wid][lane] = make_float4(__int_as_float(s), p0, p1, p2);
        __syncwarp();

        // phase 2: gather (2x unrolled)
        int j = 0;
        for (; j + 1 < m; j += 2) {
            float4 ea = buf[wid][j];
            float4 eb = buf[wid][j + 1];
            int sa = __float_as_int(ea.x);
            int sb = __float_as_int(eb.x);
            const __half* pa = &g_h16[(long)sa * HO + lane * 4];
            const __half* pb = &g_h16[(long)sb * HO + lane * 4];
            uint2 ua0 = *(const uint2*)&pa[0];
            uint2 ua1 = *(const uint2*)&pa[OUT_C];
            uint2 ua2 = *(const uint2*)&pa[2 * OUT_C];
            uint2 ub0 = *(const uint2*)&pb[0];
            uint2 ub1 = *(const uint2*)&pb[OUT_C];
            uint2 ub2 = *(const uint2*)&pb[2 * OUT_C];
            {
                float2 f01 = __half22float2(*(__half2*)&ua0.x);
                float2 f23 = __half22float2(*(__half2*)&ua0.y);
                acc[0][0] = fmaf(ea.y, f01.x, acc[0][0]);
                acc[0][1] = fmaf(ea.y, f01.y, acc[0][1]);
                acc[0][2] = fmaf(ea.y, f23.x, acc[0][2]);
                acc[0][3] = fmaf(ea.y, f23.y, acc[0][3]);
                f01 = __half22float2(*(__half2*)&ua1.x);
                f23 = __half22float2(*(__half2*)&ua1.y);
                acc[1][0] = fmaf(ea.z, f01.x, acc[1][0]);
                acc[1][1] = fmaf(ea.z, f01.y, acc[1][1]);
                acc[1][2] = fmaf(ea.z, f23.x, acc[1][2]);
                acc[1][3] = fmaf(ea.z, f23.y, acc[1][3]);
                f01 = __half22float2(*(__half2*)&ua2.x);
                f23 = __half22float2(*(__half2*)&ua2.y);
                acc[2][0] = fmaf(ea.w, f01.x, acc[2][0]);
                acc[2][1] = fmaf(ea.w, f01.y, acc[2][1]);
                acc[2][2] = fmaf(ea.w, f23.x, acc[2][2]);
                acc[2][3] = fmaf(ea.w, f23.y, acc[2][3]);
            }
            {
                float2 f01 = __half22float2(*(__half2*)&ub0.x);
                float2 f23 = __half22float2(*(__half2*)&ub0.y);
                acc[0][0] = fmaf(eb.y, f01.x, acc[0][0]);
                acc[0][1] = fmaf(eb.y, f01.y, acc[0][1]);
                acc[0][2] = fmaf(eb.y, f23.x, acc[0][2]);
                acc[0][3] = fmaf(eb.y, f23.y, acc[0][3]);
                f01 = __half22float2(*(__half2*)&ub1.x);
                f23 = __half22float2(*(__half2*)&ub1.y);
                acc[1][0] = fmaf(eb.z, f01.x, acc[1][0]);
                acc[1][1] = fmaf(eb.z, f01.y, acc[1][1]);
                acc[1][2] = fmaf(eb.z, f23.x, acc[1][2]);
                acc[1][3] = fmaf(eb.z, f23.y, acc[1][3]);
                f01 = __half22float2(*(__half2*)&ub2.x);
                f23 = __half22float2(*(__half2*)&ub2.y);
                acc[2][0] = fmaf(eb.w, f01.x, acc[2][0]);
                acc[2][1] = fmaf(eb.w, f01.y, acc[2][1]);
                acc[2][2] = fmaf(eb.w, f23.x, acc[2][2]);
                acc[2][3] = fmaf(eb.w, f23.y, acc[2][3]);
            }
        }
        if (j < m) {
            float4 ea = buf[wid][j];
            int sa = __float_as_int(ea.x);
            const __half* pa = &g_h16[(long)sa * HO + lane * 4];
            float ee[3] = {ea.y, ea.z, ea.w};
#pragma unroll
            for (int h = 0; h < 3; h++) {
                uint2 u = *(const uint2*)&pa[h * OUT_C];
                float2 f01 = __half22float2(*(__half2*)&u.x);
                float2 f23 = __half22float2(*(__half2*)&u.y);
                acc[h][0] = fmaf(ee[h], f01.x, acc[h][0]);
                acc[h][1] = fmaf(ee[h], f01.y, acc[h][1]);
                acc[h][2] = fmaf(ee[h], f23.x, acc[h][2]);
                acc[h][3] = fmaf(ee[h], f23.y, acc[h][3]);
            }
        }
        __syncwarp();
    }

    // denom = warp-sum of per-lane partials + self term
#pragma unroll
    for (int o = 16; o > 0; o >>= 1) {
        dl0 += __shfl_xor_sync(0xFFFFFFFFu, dl0, o);
        dl1 += __shfl_xor_sync(0xFFFFFFFFu, dl1, o);
        dl2 += __shfl_xor_sync(0xFFFFFFFFu, dl2, o);
    }
    float den[3] = {dl0 + e0, dl1 + e1, dl2 + e2};

    float c0s = 0.0f, c1s = 0.0f;
#pragma unroll
    for (int h = 0; h < 3; h++) {
        float inv = 1.0f / (den[h] + 1e-16f);
        int base = h * OUT_C + lane * 4;
        float4 b = *(const float4*)&bias[base];
        float r[4];
        r[0] = fmaxf(acc[h][0] * inv + b.x, 0.0f);
        r[1] = fmaxf(acc[h][1] * inv + b.y, 0.0f);
        r[2] = fmaxf(acc[h][2] * inv + b.z, 0.0f);
        r[3] = fmaxf(acc[h][3] * inv + b.w, 0.0f);
#pragma unroll
        for (int k = 0; k < 4; k++) {
            float2 w = *(const float2*)&fc_w[(base + k) * NC];
            c0s = fmaf(r[k], w.x, c0s);
            c1s = fmaf(r[k], w.y, c1s);
        }
    }
#pragma unroll
    for (int o = 16; o > 0; o >>= 1) {
        c0s += __shfl_xor_sync(0xFFFFFFFFu, c0s, o);
        c1s += __shfl_xor_sync(0xFFFFFFFFu, c1s, o);
    }
    if (lane == 0) {
        int g = batch[d];
        atomicAdd(&g_out2[g * NC + 0], c0s);
        atomicAdd(&g_out2[g * NC + 1], c1s);
        atomicAdd(&g_cnt[g], 1.0f);
    }
}

// ---------------- K7: final mean + bias ----------------
__global__ void k_final(const float* __restrict__ fc_b,
                        float* __restrict__ out) {
    int t = threadIdx.x;
    if (t >= NG * NC) return;
    int g = t >> 1;
    int c = t & 1;
    float cnt = fmaxf(g_cnt[g], 1.0f);
    out[t] = g_out2[t] / cnt + fc_b[c];
}

// ---------------- launch ----------------
extern "C" void kernel_launch(void* const* d_in, const int* in_sizes, int n_in,
                              void* d_out, int out_size) {
    const float* x       = (const float*)d_in[0];
    const int*   ei      = (const int*)  d_in[1];
    const int*   batch   = (const int*)  d_in[2];
    const float* W       = (const float*)d_in[3];
    const float* att_src = (const float*)d_in[4];
    const float* att_dst = (const float*)d_in[5];
    const float* bias    = (const float*)d_in[6];
    const float* fc_w    = (const float*)d_in[7];
    const float* fc_b    = (const float*)d_in[8];
    float* out = (float*)d_out;

    const int n = in_sizes[0] / F_IN;       // 50000
    const int E = in_sizes[1] / 2;          // 800000
    const int nblk = (n + 255) / 256;

    k_init<<<(n + 255) / 256, 256>>>(n);
    {
        dim3 grid(HEADS, (n + 127) / 128);
        k_gemm<<<grid, 256>>>(x, W, att_src, att_dst, n);
    }
    k_hist<<<(E + 255) / 256, 256>>>(ei, E);
    k_scan1<<<nblk, 256>>>(n);
    k_scan2<<<1, 256>>>(nblk);
    k_scan3<<<(n + 255) / 256, 256>>>(n);
    k_fill<<<(E + 255) / 256, 256>>>(ei, E);
    k_agg<<<(n * 32 + 255) / 256, 256>>>(batch, bias, fc_w, n);
    k_final<<<1, 128>>>(fc_b, out);
}

// round 5
// speedup vs baseline: 3.3816x; 1.0576x over previous
#include <cuda_runtime.h>
#include <cuda_fp16.h>
#include <math.h>

#define N_NODES  50000
#define F_IN     256
#define HEADS    3
#define OUT_C    128
#define HO       384      // HEADS*OUT_C
#define NG       64
#define NC       2
#define E_MAX    800000
#define SLOPE    0.2f

// ---------------- scratch (device globals; no allocs allowed) ----------------
__device__ __half g_x16[N_NODES * F_IN];     // fp16 x     (25.6 MB)
__device__ __half g_w16[F_IN * HO];          // fp16 W
__device__ __half g_h16[N_NODES * HO];       // fp16 x@W   (38.4 MB)
__device__ float g_a4_src[N_NODES * 4];      // padded [node][4] logits
__device__ float g_a4_dst[N_NODES * 4];
__device__ int   g_deg[N_NODES];
__device__ int   g_roff[N_NODES];
__device__ int   g_cursor[N_NODES];
__device__ int   g_csr[E_MAX];
__device__ int   g_scan_incl[N_NODES];
__device__ int   g_bsum[256];
__device__ float g_out2[NG * NC];
__device__ float g_cnt[NG];

// ---------------- helpers ----------------
__device__ __forceinline__ unsigned sptr(const void* p) {
    return (unsigned)__cvta_generic_to_shared(p);
}

__device__ __forceinline__ void cp_async16(unsigned dst, const void* src, bool pred) {
    int sz = pred ? 16 : 0;
    asm volatile("cp.async.cg.shared.global [%0], [%1], 16, %2;"
                 :: "r"(dst), "l"(src), "r"(sz));
}
#define CP_COMMIT() asm volatile("cp.async.commit_group;")
#define CP_WAIT1()  asm volatile("cp.async.wait_group 1;")
#define CP_WAIT0()  asm volatile("cp.async.wait_group 0;")

#define LDSM4(r0, r1, r2, r3, addr) \
    asm volatile("ldmatrix.sync.aligned.m8n8.x4.shared.b16 {%0,%1,%2,%3},[%4];" \
                 : "=r"(r0), "=r"(r1), "=r"(r2), "=r"(r3) : "r"(addr))

#define LDSM4T(r0, r1, r2, r3, addr) \
    asm volatile("ldmatrix.sync.aligned.m8n8.x4.trans.shared.b16 {%0,%1,%2,%3},[%4];" \
                 : "=r"(r0), "=r"(r1), "=r"(r2), "=r"(r3) : "r"(addr))

#define MMA16816(c, a0, a1, a2, a3, b0, b1) \
    asm volatile("mma.sync.aligned.m16n8k16.row.col.f32.f16.f16.f32 " \
                 "{%0,%1,%2,%3},{%4,%5,%6,%7},{%8,%9},{%0,%1,%2,%3};" \
                 : "+f"((c)[0]), "+f"((c)[1]), "+f"((c)[2]), "+f"((c)[3]) \
                 : "r"(a0), "r"(a1), "r"(a2), "r"(a3), "r"(b0), "r"(b1))

// ---------------- K0: init ----------------
__global__ void k_init(int n) {
    int i = blockIdx.x * blockDim.x + threadIdx.x;
    if (i < n) g_deg[i] = 0;
    if (i < NG * NC) g_out2[i] = 0.0f;
    if (i < NG) g_cnt[i] = 0.0f;
}

// ---------------- K0b: convert x, W to fp16 ----------------
__global__ void k_cvt(const float* __restrict__ x, const float* __restrict__ W,
                      int n) {
    int i = blockIdx.x * blockDim.x + threadIdx.x;
    int totalx = (n * F_IN) >> 3;
    if (i < totalx) {
        const float4* p = (const float4*)x + i * 2;
        float4 v0 = p[0], v1 = p[1];
        __half2 h0 = __floats2half2_rn(v0.x, v0.y);
        __half2 h1 = __floats2half2_rn(v0.z, v0.w);
        __half2 h2 = __floats2half2_rn(v1.x, v1.y);
        __half2 h3 = __floats2half2_rn(v1.z, v1.w);
        uint4 u;
        u.x = *(unsigned*)&h0; u.y = *(unsigned*)&h1;
        u.z = *(unsigned*)&h2; u.w = *(unsigned*)&h3;
        *(uint4*)&g_x16[i * 8] = u;
    }
    int totalw = (F_IN * HO) >> 3;   // 12288
    if (i < totalw) {
        const float4* p = (const float4*)W + i * 2;
        float4 v0 = p[0], v1 = p[1];
        __half2 h0 = __floats2half2_rn(v0.x, v0.y);
        __half2 h1 = __floats2half2_rn(v0.z, v0.w);
        __half2 h2 = __floats2half2_rn(v1.x, v1.y);
        __half2 h3 = __floats2half2_rn(v1.z, v1.w);
        uint4 u;
        u.x = *(unsigned*)&h0; u.y = *(unsigned*)&h1;
        u.z = *(unsigned*)&h2; u.w = *(unsigned*)&h3;
        *(uint4*)&g_w16[i * 8] = u;
    }
}

// ---------------- K1: tensor-core GEMM (fp16 in, cp.async double-buffered) ---
// grid (HEADS, ceil(n/128)); block 256 = 8 warps; tile 128x128, BK=32.
__global__ void __launch_bounds__(256) k_gemm(const float* __restrict__ att_src,
                                              const float* __restrict__ att_dst,
                                              int n) {
    __shared__ __half Ah[2][128 * 40];   // stride 40 halves (80 B)
    __shared__ __half Bh[2][32 * 136];   // stride 136 halves (272 B)
    __shared__ float Ps[128][4];
    __shared__ float Pd[128][4];

    const int head = blockIdx.x;
    const int row0 = blockIdx.y * 128;
    const int t = threadIdx.x;
    const int lane = t & 31;
    const int wid = t >> 5;
    const int warp_m = wid & 1;
    const int warp_n = wid >> 1;

    float acc[4][4][4];
#pragma unroll
    for (int mf = 0; mf < 4; mf++)
#pragma unroll
        for (int nf = 0; nf < 4; nf++)
#pragma unroll
            for (int r = 0; r < 4; r++) acc[mf][nf][r] = 0.0f;

    // async tile issue: A = 512 chunks of 16B, B = 512 chunks of 16B, 2+2/thread
    auto issue = [&](int st, int kk) {
#pragma unroll
        for (int l = 0; l < 2; l++) {
            int q = t + l * 256;
            int row = q >> 2, seg = q & 3;
            bool pred = (row0 + row) < n;
            const __half* src = &g_x16[(long)(row0 + row) * F_IN + kk + seg * 8];
            cp_async16(sptr(&Ah[st][row * 40 + seg * 8]), src, pred);
        }
#pragma unroll
        for (int l = 0; l < 2; l++) {
            int q = t + l * 256;
            int kr = q >> 4, seg = q & 15;
            const __half* src = &g_w16[(long)(kk + kr) * HO + head * 128 + seg * 8];
            cp_async16(sptr(&Bh[st][kr * 136 + seg * 8]), src, true);
        }
        CP_COMMIT();
    };

    issue(0, 0);

    const int NIT = F_IN / 32;   // 8
    for (int i = 0; i < NIT; i++) {
        int st = i & 1;
        if (i + 1 < NIT) { issue((i + 1) & 1, (i + 1) * 32); CP_WAIT1(); }
        else             { CP_WAIT0(); }
        __syncthreads();

#pragma unroll
        for (int s = 0; s < 2; s++) {
            unsigned a[4][4];
#pragma unroll
            for (int mf = 0; mf < 4; mf++) {
                unsigned addr = sptr(&Ah[st][(warp_m * 64 + mf * 16 + (lane & 15)) * 40 +
                                            s * 16 + (lane >> 4) * 8]);
                LDSM4(a[mf][0], a[mf][1], a[mf][2], a[mf][3], addr);
            }
            unsigned b[2][4];
#pragma unroll
            for (int nf2 = 0; nf2 < 2; nf2++) {
                unsigned addr = sptr(&Bh[st][(s * 16 + (lane & 15)) * 136 +
                                            warp_n * 32 + nf2 * 16 + ((lane & 16) ? 8 : 0)]);
                LDSM4T(b[nf2][0], b[nf2][1], b[nf2][2], b[nf2][3], addr);
            }
#pragma unroll
            for (int mf = 0; mf < 4; mf++)
#pragma unroll
                for (int nf = 0; nf < 4; nf++) {
                    int nf2 = nf >> 1;
                    int bo = (nf & 1) * 2;
                    MMA16816(acc[mf][nf], a[mf][0], a[mf][1], a[mf][2], a[mf][3],
                             b[nf2][bo], b[nf2][bo + 1]);
                }
        }
        __syncthreads();
    }

    // ---- epilogue: logits + fp16 store ----
    float avs[4][2], avd[4][2];
#pragma unroll
    for (int nf = 0; nf < 4; nf++)
#pragma unroll
        for (int j = 0; j < 2; j++) {
            int c = head * 128 + warp_n * 32 + nf * 8 + (lane & 3) * 2 + j;
            avs[nf][j] = att_src[c];
            avd[nf][j] = att_dst[c];
        }

#pragma unroll
    for (int mf = 0; mf < 4; mf++)
#pragma unroll
        for (int rh = 0; rh < 2; rh++) {
            float ps = 0.0f, pd = 0.0f;
#pragma unroll
            for (int nf = 0; nf < 4; nf++)
#pragma unroll
                for (int j = 0; j < 2; j++) {
                    float v = acc[mf][nf][rh * 2 + j];
                    ps = fmaf(v, avs[nf][j], ps);
                    pd = fmaf(v, avd[nf][j], pd);
                }
            ps += __shfl_xor_sync(0xFFFFFFFFu, ps, 1);
            ps += __shfl_xor_sync(0xFFFFFFFFu, ps, 2);
            pd += __shfl_xor_sync(0xFFFFFFFFu, pd, 1);
            pd += __shfl_xor_sync(0xFFFFFFFFu, pd, 2);
            int rloc = warp_m * 64 + mf * 16 + (lane >> 2) + rh * 8;
            if ((lane & 3) == 0) { Ps[rloc][warp_n] = ps; Pd[rloc][warp_n] = pd; }
            int grow = row0 + rloc;
            if (grow < n) {
#pragma unroll
                for (int nf = 0; nf < 4; nf++) {
                    __half2 hh = __floats2half2_rn(acc[mf][nf][rh * 2],
                                                   acc[mf][nf][rh * 2 + 1]);
                    *(__half2*)&g_h16[(long)grow * HO + head * 128 + warp_n * 32 +
                                      nf * 8 + (lane & 3) * 2] = hh;
                }
            }
        }
    __syncthreads();

    int r = t & 127;
    int grow = row0 + r;
    if (grow < n) {
        if (t < 128) {
            g_a4_src[grow * 4 + head] = Ps[r][0] + Ps[r][1] + Ps[r][2] + Ps[r][3];
        } else {
            g_a4_dst[grow * 4 + head] = Pd[r][0] + Pd[r][1] + Pd[r][2] + Pd[r][3];
        }
    }
}

// ---------------- K3: degree histogram (4 edges/thread) ----------------
__global__ void k_hist(const int* __restrict__ ei, int E) {
    int i = (blockIdx.x * blockDim.x + threadIdx.x) * 4;
    if (i + 3 < E) {
        int4 d = *(const int4*)&ei[E + i];
        atomicAdd(&g_deg[d.x], 1);
        atomicAdd(&g_deg[d.y], 1);
        atomicAdd(&g_deg[d.z], 1);
        atomicAdd(&g_deg[d.w], 1);
    } else {
        for (int k = 0; k < 4 && i + k < E; k++)
            atomicAdd(&g_deg[ei[E + i + k]], 1);
    }
}

// ---------------- K4: scans (warp-shuffle, 1024 elems/block) -----------------
__global__ void k_scan1(int n) {
    __shared__ int wsum[8];
    int b = blockIdx.x, t = threadIdx.x;
    int base = b * 1024 + t * 4;
    int4 v = make_int4(0, 0, 0, 0);
    if (base + 3 < n) v = *(const int4*)&g_deg[base];
    else {
        if (base < n)     v.x = g_deg[base];
        if (base + 1 < n) v.y = g_deg[base + 1];
        if (base + 2 < n) v.z = g_deg[base + 2];
    }
    int s0 = v.x, s1 = s0 + v.y, s2 = s1 + v.z, s3 = s2 + v.w;
    int lane = t & 31, wd = t >> 5;
    int tot = s3;
#pragma unroll
    for (int o = 1; o < 32; o <<= 1) {
        int u = __shfl_up_sync(0xFFFFFFFFu, tot, o);
        if (lane >= o) tot += u;
    }
    if (lane == 31) wsum[wd] = tot;
    __syncthreads();
    if (t < 8) {
        int w = wsum[t];
#pragma unroll
        for (int o = 1; o < 8; o <<= 1) {
            int u = __shfl_up_sync(0x000000FFu, w, o);
            if (t >= o) w += u;
        }
        wsum[t] = w;
    }
    __syncthreads();
    int offset = (wd > 0 ? wsum[wd - 1] : 0) + (tot - s3);
    if (base < n) {
        if (base + 3 < n) {
            *(int4*)&g_scan_incl[base] =
                make_int4(offset + s0, offset + s1, offset + s2, offset + s3);
        } else {
            g_scan_incl[base] = offset + s0;
            if (base + 1 < n) g_scan_incl[base + 1] = offset + s1;
            if (base + 2 < n) g_scan_incl[base + 2] = offset + s2;
        }
    }
    if (t == 255) g_bsum[b] = wsum[7];
}

__global__ void k_scan2(int nblk) {
    __shared__ int s[256];
    int t = threadIdx.x;
    int orig = (t < nblk) ? g_bsum[t] : 0;
    s[t] = orig;
    __syncthreads();
#pragma unroll
    for (int off = 1; off < 256; off <<= 1) {
        int u = (t >= off) ? s[t - off] : 0;
        __syncthreads();
        s[t] += u;
        __syncthreads();
    }
    g_bsum[t] = s[t] - orig;
}

__global__ void k_scan3(int n) {
    int i = blockIdx.x * blockDim.x + threadIdx.x;
    if (i >= n) return;
    int r = g_scan_incl[i] - g_deg[i] + g_bsum[i >> 10];
    g_roff[i] = r;
    g_cursor[i] = r;
}

// ---------------- K5: CSR fill (4 edges/thread) ----------------
__global__ void k_fill(const int* __restrict__ ei, int E) {
    int i = (blockIdx.x * blockDim.x + threadIdx.x) * 4;
    if (i + 3 < E) {
        int4 s = *(const int4*)&ei[i];
        int4 d = *(const int4*)&ei[E + i];
        int p0 = atomicAdd(&g_cursor[d.x], 1); g_csr[p0] = s.x;
        int p1 = atomicAdd(&g_cursor[d.y], 1); g_csr[p1] = s.y;
        int p2 = atomicAdd(&g_cursor[d.z], 1); g_csr[p2] = s.z;
        int p3 = atomicAdd(&g_cursor[d.w], 1); g_csr[p3] = s.w;
    } else {
        for (int k = 0; k < 4 && i + k < E; k++) {
            int pos = atomicAdd(&g_cursor[ei[E + i + k]], 1);
            g_csr[pos] = ei[i + k];
        }
    }
}

// ---------------- K6: fused softmax + aggregate + relu + FC-project ----------
__global__ void __launch_bounds__(256) k_agg(const int* __restrict__ batch,
                                             const float* __restrict__ bias,
                                             const float* __restrict__ fc_w,
                                             int n) {
    __shared__ float4 buf[8][32];

    int d = (blockIdx.x * blockDim.x + threadIdx.x) >> 5;
    int lane = threadIdx.x & 31;
    int wid = (threadIdx.x >> 5);
    if (d >= n) return;

    float ad = (lane < 3) ? g_a4_dst[d * 4 + lane] : 0.0f;
    float adst0 = __shfl_sync(0xFFFFFFFFu, ad, 0);
    float adst1 = __shfl_sync(0xFFFFFFFFu, ad, 1);
    float adst2 = __shfl_sync(0xFFFFFFFFu, ad, 2);

    float exl = 0.0f;
    if (lane < 3) {
        float v = g_a4_src[d * 4 + lane] + ad;
        v = v > 0.0f ? v : SLOPE * v;
        exl = __expf(v);
    }
    float e0 = __shfl_sync(0xFFFFFFFFu, exl, 0);
    float e1 = __shfl_sync(0xFFFFFFFFu, exl, 1);
    float e2 = __shfl_sync(0xFFFFFFFFu, exl, 2);

    float acc[3][4];
    {
        const __half* hp = &g_h16[(long)d * HO + lane * 4];
        float ee[3] = {e0, e1, e2};
#pragma unroll
        for (int h = 0; h < 3; h++) {
            uint2 u = *(const uint2*)&hp[h * OUT_C];
            float2 f01 = __half22float2(*(__half2*)&u.x);
            float2 f23 = __half22float2(*(__half2*)&u.y);
            acc[h][0] = ee[h] * f01.x;
            acc[h][1] = ee[h] * f01.y;
            acc[h][2] = ee[h] * f23.x;
            acc[h][3] = ee[h] * f23.y;
        }
    }

    int start = g_roff[d];
    int cnt = g_deg[d];
    float dl0 = 0.0f, dl1 = 0.0f, dl2 = 0.0f;

    for (int c0 = 0; c0 < cnt; c0 += 32) {
        int m = min(32, cnt - c0);
        int s = 0;
        float p0 = 0.0f, p1 = 0.0f, p2 = 0.0f;
        if (lane < m) {
            s = g_csr[start + c0 + lane];
            float4 a4 = *(const float4*)&g_a4_src[s * 4];
            float v0 = a4.x + adst0; v0 = v0 > 0.0f ? v0 : SLOPE * v0;
            float v1 = a4.y + adst1; v1 = v1 > 0.0f ? v1 : SLOPE * v1;
            float v2 = a4.z + adst2; v2 = v2 > 0.0f ? v2 : SLOPE * v2;
            p0 = __expf(v0); p1 = __expf(v1); p2 = __expf(v2);
            dl0 += p0; dl1 += p1; dl2 += p2;
        }
        buf[wid][lane] = make_float4(__int_as_float(s), p0, p1, p2);
        __syncwarp();

        int j = 0;
        for (; j + 4 <= m; j += 4) {
            float4 e[4];
            int sv[4];
            uint2 u[4][3];
#pragma unroll
            for (int q = 0; q < 4; q++) {
                e[q] = buf[wid][j + q];
                sv[q] = __float_as_int(e[q].x);
            }
#pragma unroll
            for (int q = 0; q < 4; q++) {
                const __half* p = &g_h16[(long)sv[q] * HO + lane * 4];
                u[q][0] = *(const uint2*)&p[0];
                u[q][1] = *(const uint2*)&p[OUT_C];
                u[q][2] = *(const uint2*)&p[2 * OUT_C];
            }
#pragma unroll
            for (int q = 0; q < 4; q++) {
                float w[3] = {e[q].y, e[q].z, e[q].w};
#pragma unroll
                for (int h = 0; h < 3; h++) {
                    float2 f01 = __half22float2(*(__half2*)&u[q][h].x);
                    float2 f23 = __half22float2(*(__half2*)&u[q][h].y);
                    acc[h][0] = fmaf(w[h], f01.x, acc[h][0]);
                    acc[h][1] = fmaf(w[h], f01.y, acc[h][1]);
                    acc[h][2] = fmaf(w[h], f23.x, acc[h][2]);
                    acc[h][3] = fmaf(w[h], f23.y, acc[h][3]);
                }
            }
        }
        for (; j < m; j++) {
            float4 ea = buf[wid][j];
            int sa = __float_as_int(ea.x);
            const __half* pa = &g_h16[(long)sa * HO + lane * 4];
            float ee[3] = {ea.y, ea.z, ea.w};
#pragma unroll
            for (int h = 0; h < 3; h++) {
                uint2 u2 = *(const uint2*)&pa[h * OUT_C];
                float2 f01 = __half22float2(*(__half2*)&u2.x);
                float2 f23 = __half22float2(*(__half2*)&u2.y);
                acc[h][0] = fmaf(ee[h], f01.x, acc[h][0]);
                acc[h][1] = fmaf(ee[h], f01.y, acc[h][1]);
                acc[h][2] = fmaf(ee[h], f23.x, acc[h][2]);
                acc[h][3] = fmaf(ee[h], f23.y, acc[h][3]);
            }
        }
        __syncwarp();
    }

#pragma unroll
    for (int o = 16; o > 0; o >>= 1) {
        dl0 += __shfl_xor_sync(0xFFFFFFFFu, dl0, o);
        dl1 += __shfl_xor_sync(0xFFFFFFFFu, dl1, o);
        dl2 += __shfl_xor_sync(0xFFFFFFFFu, dl2, o);
    }
    float den[3] = {dl0 + e0, dl1 + e1, dl2 + e2};

    float c0s = 0.0f, c1s = 0.0f;
#pragma unroll
    for (int h = 0; h < 3; h++) {
        float inv = 1.0f / (den[h] + 1e-16f);
        int base = h * OUT_C + lane * 4;
        float4 b = *(const float4*)&bias[base];
        float r[4];
        r[0] = fmaxf(acc[h][0] * inv + b.x, 0.0f);
        r[1] = fmaxf(acc[h][1] * inv + b.y, 0.0f);
        r[2] = fmaxf(acc[h][2] * inv + b.z, 0.0f);
        r[3] = fmaxf(acc[h][3] * inv + b.w, 0.0f);
#pragma unroll
        for (int k = 0; k < 4; k++) {
            float2 w = *(const float2*)&fc_w[(base + k) * NC];
            c0s = fmaf(r[k], w.x, c0s);
            c1s = fmaf(r[k], w.y, c1s);
        }
    }
#pragma unroll
    for (int o = 16; o > 0; o >>= 1) {
        c0s += __shfl_xor_sync(0xFFFFFFFFu, c0s, o);
        c1s += __shfl_xor_sync(0xFFFFFFFFu, c1s, o);
    }
    if (lane == 0) {
        int g = batch[d];
        atomicAdd(&g_out2[g * NC + 0], c0s);
        atomicAdd(&g_out2[g * NC + 1], c1s);
        atomicAdd(&g_cnt[g], 1.0f);
    }
}

// ---------------- K7: final mean + bias ----------------
__global__ void k_final(const float* __restrict__ fc_b,
                        float* __restrict__ out) {
    int t = threadIdx.x;
    if (t >= NG * NC) return;
    int g = t >> 1;
    int c = t & 1;
    float cnt = fmaxf(g_cnt[g], 1.0f);
    out[t] = g_out2[t] / cnt + fc_b[c];
}

// ---------------- launch ----------------
extern "C" void kernel_launch(void* const* d_in, const int* in_sizes, int n_in,
                              void* d_out, int out_size) {
    const float* x       = (const float*)d_in[0];
    const int*   ei      = (const int*)  d_in[1];
    const int*   batch   = (const int*)  d_in[2];
    const float* W       = (const float*)d_in[3];
    const float* att_src = (const float*)d_in[4];
    const float* att_dst = (const float*)d_in[5];
    const float* bias    = (const float*)d_in[6];
    const float* fc_w    = (const float*)d_in[7];
    const float* fc_b    = (const float*)d_in[8];
    float* out = (float*)d_out;

    const int n = in_sizes[0] / F_IN;       // 50000
    const int E = in_sizes[1] / 2;          // 800000
    const int nblk = (n + 1023) / 1024;     // 49

    k_init<<<(n + 255) / 256, 256>>>(n);
    {
        int totalx = (n * F_IN) >> 3;
        k_cvt<<<(totalx + 255) / 256, 256>>>(x, W, n);
    }
    {
        dim3 grid(HEADS, (n + 127) / 128);
        k_gemm<<<grid, 256>>>(att_src, att_dst, n);
    }
    k_hist<<<(E / 4 + 255) / 256, 256>>>(ei, E);
    k_scan1<<<nblk, 256>>>(n);
    k_scan2<<<1, 256>>>(nblk);
    k_scan3<<<(n + 255) / 256, 256>>>(n);
    k_fill<<<(E / 4 + 255) / 256, 256>>>(ei, E);
    k_agg<<<(n * 32 + 255) / 256, 256>>>(batch, bias, fc_w, n);
    k_final<<<1, 128>>>(fc_b, out);
}